// round 1
// baseline (speedup 1.0000x reference)
#include <cuda_runtime.h>

#define IH 1024
#define IW 1024
#define NJMAX 510      // last valid patch index (nj = 511)
#define TJ 16          // owned patch rows per block
#define TK 16          // owned patch cols per block
// halo patches: 17x17 ; input tile: 36x36 ; output tile: 32x32

#define SIN_W 36
#define NPAT 289              // 17*17
#define DEC_STRIDE 290        // padded (conflict-free: consecutive patch -> consecutive bank)

__device__ __forceinline__ float fast_sigmoid(float x) {
    return 1.0f / (1.0f + __expf(-x));
}

__global__ __launch_bounds__(256, 6)
void ae_kernel(const float* __restrict__ img,
               const float* __restrict__ w_conv,  // (2,1,2,2)
               const float* __restrict__ b_conv,  // (2,)
               const float* __restrict__ W_b,     // (2,2)
               const float* __restrict__ b_b,     // (2,)
               const float* __restrict__ W_d,     // (2,1,2,2)
               const float* __restrict__ b_d,     // (1,)
               float* __restrict__ out)
{
    __shared__ float s_in[SIN_W * SIN_W];
    __shared__ float s_dec[16][DEC_STRIDE];

    const int tid = threadIdx.x;
    const int bk = blockIdx.x;     // patch-col tile
    const int bj = blockIdx.y;     // patch-row tile
    const int b  = blockIdx.z;     // batch

    const int j0 = bj * TJ;
    const int k0 = bk * TK;
    const int jlo = max(j0 - 1, 0);
    const int jhi = min(j0 + TJ - 1, NJMAX);
    const int klo = max(k0 - 1, 0);
    const int khi = min(k0 + TK - 1, NJMAX);
    const int npj = jhi - jlo + 1;
    const int npk = khi - klo + 1;

    const int rbase = 2 * j0 - 2;  // abs input row of s_in row 0
    const int cbase = 2 * k0 - 2;

    // ---- load input halo tile ----
    const float* imgb = img + (size_t)b * (IH * IW);
    for (int idx = tid; idx < SIN_W * SIN_W; idx += 256) {
        int lr = idx / SIN_W;
        int lc = idx - lr * SIN_W;
        int gr = rbase + lr;
        int gc = cbase + lc;
        float v = 0.0f;
        if (gr >= 0 && gr < IH && gc >= 0 && gc < IW)
            v = __ldg(imgb + gr * IW + gc);
        s_in[idx] = v;
    }

    // ---- load tiny weights to registers (L1-resident) ----
    float wc0[4], wc1[4], wd0[4], wd1[4];
    #pragma unroll
    for (int i = 0; i < 4; i++) {
        wc0[i] = __ldg(w_conv + i);
        wc1[i] = __ldg(w_conv + 4 + i);
        wd0[i] = __ldg(W_d + i);
        wd1[i] = __ldg(W_d + 4 + i);
    }
    const float bc0 = __ldg(b_conv + 0), bc1 = __ldg(b_conv + 1);
    const float wb00 = __ldg(W_b + 0), wb01 = __ldg(W_b + 1);
    const float wb10 = __ldg(W_b + 2), wb11 = __ldg(W_b + 3);
    const float bb0 = __ldg(b_b + 0), bb1 = __ldg(b_b + 1);
    const float bd = __ldg(b_d);
    const float sconst = fast_sigmoid(bd);

    __syncthreads();

    // ---- per-patch pipeline: conv -> relu -> maxpool(argmax) -> dense -> unpool -> deconv -> sigmoid ----
    for (int p = tid; p < NPAT; p += 256) {
        int pj = p / 17;
        int pk = p - pj * 17;
        if (pj >= npj || pk >= npk) continue;
        int j = jlo + pj;
        int k = klo + pk;
        int r0 = 2 * j - rbase;   // local row in s_in
        int c0 = 2 * k - cbase;

        float x[4][4];
        #pragma unroll
        for (int r = 0; r < 4; r++)
            #pragma unroll
            for (int c = 0; c < 4; c++)
                x[r][c] = s_in[(r0 + r) * SIN_W + (c0 + c)];

        // conv: 2 channels, 2x2 kernel, stride 2 -> cv[ch][i*2+jb]
        float cv0[4], cv1[4];
        #pragma unroll
        for (int i = 0; i < 2; i++)
            #pragma unroll
            for (int jb = 0; jb < 2; jb++) {
                float a = x[2*i][2*jb],   bx = x[2*i][2*jb+1];
                float c2 = x[2*i+1][2*jb], d = x[2*i+1][2*jb+1];
                float v0 = fmaf(wc0[0], a, fmaf(wc0[1], bx, fmaf(wc0[2], c2, fmaf(wc0[3], d, bc0))));
                float v1 = fmaf(wc1[0], a, fmaf(wc1[1], bx, fmaf(wc1[2], c2, fmaf(wc1[3], d, bc1))));
                cv0[i*2+jb] = fmaxf(v0, 0.0f);
                cv1[i*2+jb] = fmaxf(v1, 0.0f);
            }

        // argmax (first-max semantics: strict >)
        int am0 = 0, am1 = 0;
        float mv0 = cv0[0], mv1 = cv1[0];
        #pragma unroll
        for (int e = 1; e < 4; e++) {
            if (cv0[e] > mv0) { mv0 = cv0[e]; am0 = e; }
            if (cv1[e] > mv1) { mv1 = cv1[e]; am1 = e; }
        }

        // dense + relu
        float z0 = fmaxf(fmaf(mv0, wb00, fmaf(mv1, wb01, bb0)), 0.0f);
        float z1 = fmaxf(fmaf(mv0, wb10, fmaf(mv1, wb11, bb1)), 0.0f);

        // deconv + sigmoid, per 2x2 output block
        int pidx = pj * 17 + pk;
        #pragma unroll
        for (int blk = 0; blk < 4; blk++) {
            float t0 = (blk == am0) ? z0 : 0.0f;
            float t1 = (blk == am1) ? z1 : 0.0f;
            int bi = blk >> 1, bjq = blk & 1;
            int ebase = (2 * bi) * 4 + 2 * bjq;   // pixel slot of (p_=0,q=0)
            if (t0 == 0.0f && t1 == 0.0f) {
                s_dec[ebase + 0][pidx] = sconst;
                s_dec[ebase + 1][pidx] = sconst;
                s_dec[ebase + 4][pidx] = sconst;
                s_dec[ebase + 5][pidx] = sconst;
            } else {
                #pragma unroll
                for (int pq = 0; pq < 4; pq++) {
                    int p_ = pq >> 1, q = pq & 1;
                    float v = fmaf(t0, wd0[pq], fmaf(t1, wd1[pq], bd));
                    s_dec[ebase + p_ * 4 + q][pidx] = fast_sigmoid(v);
                }
            }
        }
    }

    __syncthreads();

    // ---- gather: each output pixel sums its <=4 covering-patch contributions ----
    float* outb = out + (size_t)b * (IH * IW);
    #pragma unroll
    for (int it = 0; it < 4; it++) {
        int p = tid + it * 256;           // 0..1023
        int lh = p >> 5, lw = p & 31;
        int h = 2 * j0 + lh;
        int w = 2 * k0 + lw;

        int jsrt = max((h - 2) >> 1, 0);
        int jend = min(h >> 1, NJMAX);
        int ksrt = max((w - 2) >> 1, 0);
        int kend = min(w >> 1, NJMAX);

        float sum = 0.0f;
        for (int j = jsrt; j <= jend; j++) {
            int er = (h - 2 * j) * 4;
            int prow = (j - jlo) * 17;
            for (int k = ksrt; k <= kend; k++) {
                int e = er + (w - 2 * k);
                sum += s_dec[e][prow + (k - klo)];
            }
        }
        int cnt = (jend - jsrt + 1) * (kend - ksrt + 1);  // 1,2,4 -> exact division
        outb[h * IW + w] = sum / (float)cnt;
    }
}

extern "C" void kernel_launch(void* const* d_in, const int* in_sizes, int n_in,
                              void* d_out, int out_size) {
    const float* img    = (const float*)d_in[0];
    const float* w_conv = (const float*)d_in[1];
    const float* b_conv = (const float*)d_in[2];
    const float* W_b    = (const float*)d_in[3];
    const float* b_b    = (const float*)d_in[4];
    const float* W_d    = (const float*)d_in[5];
    const float* b_d    = (const float*)d_in[6];
    float* out = (float*)d_out;

    dim3 grid(32, 32, 8);   // (patch-col tiles, patch-row tiles, batch)
    dim3 block(256);
    ae_kernel<<<grid, block>>>(img, w_conv, b_conv, W_b, b_b, W_d, b_d, out);
}

// round 2
// speedup vs baseline: 1.4039x; 1.4039x over previous
#include <cuda_runtime.h>

#define IH 1024
#define IW 1024
#define NJMAX 510          // last valid patch index (nj = nk = 511)
#define TJ 15              // owned patch rows/cols per block
#define SIN_W 34           // input tile: 34x34 (16 halo patch rows -> 2*16+2)
#define DSTR 20            // dec stride in floats (conflict-free STS.128)

__device__ __forceinline__ float ex2f(float x) {
    float y; asm("ex2.approx.f32 %0, %1;" : "=f"(y) : "f"(x)); return y;
}
__device__ __forceinline__ float rcpf(float x) {
    float y; asm("rcp.approx.f32 %0, %1;" : "=f"(y) : "f"(x)); return y;
}
// sigmoid(x) = 1/(1+2^m) where m = -x*log2(e) is passed pre-folded
__device__ __forceinline__ float sig_from_m(float m) {
    return rcpf(1.0f + ex2f(m));
}

__global__ __launch_bounds__(256, 5)
void ae_kernel(const float* __restrict__ img,
               const float* __restrict__ w_conv,  // (2,1,2,2)
               const float* __restrict__ b_conv,  // (2,)
               const float* __restrict__ W_b,     // (2,2)
               const float* __restrict__ b_b,     // (2,)
               const float* __restrict__ W_d,     // (2,1,2,2)
               const float* __restrict__ b_d,     // (1,)
               float* __restrict__ out)
{
    __shared__ float s_in[SIN_W * SIN_W];      // 4.6 KB
    __shared__ float s_dec[256 * DSTR];        // 20 KB

    const int tid  = threadIdx.x;
    const int lane = tid & 31;
    const int wid  = tid >> 5;
    const int bk = blockIdx.x, bj = blockIdx.y, b = blockIdx.z;

    const int j0 = bj * TJ;
    const int k0 = bk * TJ;
    const int rbase = 2 * j0 - 2;    // input row of s_in row 0 (may be -2)
    const int cbase = 2 * k0 - 2;

    // ---- load 34x34 input halo tile (zero-padded) ----
    const float* imgb = img + (size_t)b * (IH * IW);
    for (int lr = wid; lr < SIN_W; lr += 8) {
        const int gr = rbase + lr;
        const bool rok = (unsigned)gr < 1024u;
        const float* src = imgb + (size_t)gr * IW;
        float* drow = s_in + lr * SIN_W;
        int gc = cbase + lane;
        drow[lane] = (rok && (unsigned)gc < 1024u) ? __ldg(src + gc) : 0.0f;
        if (lane < 2) {
            gc = cbase + 32 + lane;
            drow[32 + lane] = (rok && (unsigned)gc < 1024u) ? __ldg(src + gc) : 0.0f;
        }
    }

    // ---- tiny weights -> registers (uniform, L1-resident) ----
    const float LOG2E = 1.4426950408889634f;
    float wc0[4], wc1[4], wd0m[4], wd1m[4];
    #pragma unroll
    for (int i = 0; i < 4; i++) {
        wc0[i]  = __ldg(w_conv + i);
        wc1[i]  = __ldg(w_conv + 4 + i);
        wd0m[i] = __ldg(W_d + i)     * (-LOG2E);
        wd1m[i] = __ldg(W_d + 4 + i) * (-LOG2E);
    }
    const float bc0 = __ldg(b_conv + 0), bc1 = __ldg(b_conv + 1);
    const float wb00 = __ldg(W_b + 0), wb01 = __ldg(W_b + 1);
    const float wb10 = __ldg(W_b + 2), wb11 = __ldg(W_b + 3);
    const float bb0 = __ldg(b_b + 0), bb1 = __ldg(b_b + 1);
    const float bdm = __ldg(b_d) * (-LOG2E);
    const float sconst = sig_from_m(bdm);   // sigmoid(b_d)

    __syncthreads();

    // ================= per-patch pipeline: exactly 1 patch per thread ============
    {
        const int pj = tid >> 4;          // halo patch row 0..15
        const int pk = tid & 15;          // halo patch col 0..15
        const int r0 = 2 * pj;            // local row in s_in
        const int c0 = 2 * pk;

        float cv0[4], cv1[4];
        #pragma unroll
        for (int i = 0; i < 2; i++) {
            const float* row0 = &s_in[(r0 + 2 * i) * SIN_W + c0];
            const float* row1 = row0 + SIN_W;
            float2 a01 = *(const float2*)(row0);
            float2 a23 = *(const float2*)(row0 + 2);
            float2 b01 = *(const float2*)(row1);
            float2 b23 = *(const float2*)(row1 + 2);
            // block (i, 0)
            float v0 = fmaf(wc0[0], a01.x, fmaf(wc0[1], a01.y, fmaf(wc0[2], b01.x, fmaf(wc0[3], b01.y, bc0))));
            float v1 = fmaf(wc1[0], a01.x, fmaf(wc1[1], a01.y, fmaf(wc1[2], b01.x, fmaf(wc1[3], b01.y, bc1))));
            cv0[2*i + 0] = fmaxf(v0, 0.0f);
            cv1[2*i + 0] = fmaxf(v1, 0.0f);
            // block (i, 1)
            v0 = fmaf(wc0[0], a23.x, fmaf(wc0[1], a23.y, fmaf(wc0[2], b23.x, fmaf(wc0[3], b23.y, bc0))));
            v1 = fmaf(wc1[0], a23.x, fmaf(wc1[1], a23.y, fmaf(wc1[2], b23.x, fmaf(wc1[3], b23.y, bc1))));
            cv0[2*i + 1] = fmaxf(v0, 0.0f);
            cv1[2*i + 1] = fmaxf(v1, 0.0f);
        }

        // argmax (first-max semantics: strict >)
        int am0 = 0, am1 = 0;
        float mv0 = cv0[0], mv1 = cv1[0];
        #pragma unroll
        for (int e = 1; e < 4; e++) {
            if (cv0[e] > mv0) { mv0 = cv0[e]; am0 = e; }
            if (cv1[e] > mv1) { mv1 = cv1[e]; am1 = e; }
        }

        // dense + relu
        const float z0 = fmaxf(fmaf(mv0, wb00, fmaf(mv1, wb01, bb0)), 0.0f);
        const float z1 = fmaxf(fmaf(mv0, wb10, fmaf(mv1, wb11, bb1)), 0.0f);
        const float zz1 = (am0 == am1) ? z1 : 0.0f;

        // 8 unconditional sigmoids (divergence-free MUFU usage)
        float s0[4], s1[4];
        #pragma unroll
        for (int pq = 0; pq < 4; pq++) {
            s0[pq] = sig_from_m(fmaf(z0, wd0m[pq], fmaf(zz1, wd1m[pq], bdm)));
            s1[pq] = sig_from_m(fmaf(z1, wd1m[pq], bdm));
        }

        // write dec tile: [patch][20] layout, constant fill then overwrite active quadrants
        float* dp = s_dec + tid * DSTR;
        const float4 sc4 = make_float4(sconst, sconst, sconst, sconst);
        *(float4*)(dp + 0)  = sc4;
        *(float4*)(dp + 4)  = sc4;
        *(float4*)(dp + 8)  = sc4;
        *(float4*)(dp + 12) = sc4;

        const int eb0 = (am0 >> 1) * 8 + (am0 & 1) * 2;
        *(float2*)(dp + eb0)     = make_float2(s0[0], s0[1]);
        *(float2*)(dp + eb0 + 4) = make_float2(s0[2], s0[3]);
        if (am1 != am0) {
            const int eb1 = (am1 >> 1) * 8 + (am1 & 1) * 2;
            *(float2*)(dp + eb1)     = make_float2(s1[0], s1[1]);
            *(float2*)(dp + eb1 + 4) = make_float2(s1[2], s1[3]);
        }
    }

    __syncthreads();

    // ================= gather: one 2x2 output cell per thread =====================
    float* outb = out + (size_t)b * (IH * IW);
    const int a  = tid >> 4;      // cell row 0..14 (15 invalid)
    const int cb = tid & 15;      // cell col 0..14 (15 invalid)
    const bool interior = (bj >= 1) & (bj <= 33) & (bk >= 1) & (bk <= 33);

    if (a < 15 && cb < 15) {
        if (interior) {
            const float* p00 = s_dec + (a * 16 + cb) * DSTR;   // halo patch (a,   b)
            const float* p01 = p00 + DSTR;                     // (a,   b+1)
            const float* p10 = p00 + 16 * DSTR;                // (a+1, b)
            const float* p11 = p10 + DSTR;                     // (a+1, b+1)
            float2 t00a = *(const float2*)(p00 + 10), t00b = *(const float2*)(p00 + 14);
            float2 t01a = *(const float2*)(p01 + 8),  t01b = *(const float2*)(p01 + 12);
            float2 t10a = *(const float2*)(p10 + 2),  t10b = *(const float2*)(p10 + 6);
            float2 t11a = *(const float2*)(p11 + 0),  t11b = *(const float2*)(p11 + 4);

            float pix00 = (t00a.x + t01a.x) + (t10a.x + t11a.x);
            float pix01 = (t00a.y + t01a.y) + (t10a.y + t11a.y);
            float pix10 = (t00b.x + t01b.x) + (t10b.x + t11b.x);
            float pix11 = (t00b.y + t01b.y) + (t10b.y + t11b.y);

            const int h = 2 * j0 + 2 * a;
            const int w = 2 * k0 + 2 * cb;
            *(float2*)&outb[(size_t)h * IW + w]       = make_float2(pix00 * 0.25f, pix01 * 0.25f);
            *(float2*)&outb[(size_t)(h + 1) * IW + w] = make_float2(pix10 * 0.25f, pix11 * 0.25f);
        } else {
            #pragma unroll
            for (int di = 0; di < 2; di++) {
                #pragma unroll
                for (int dj = 0; dj < 2; dj++) {
                    const int h = 2 * j0 + 2 * a + di;
                    const int w = 2 * k0 + 2 * cb + dj;
                    if (h < IH && w < IW) {
                        const int jsrt = max((h - 2) >> 1, 0);
                        const int jend = min(h >> 1, NJMAX);
                        const int ksrt = max((w - 2) >> 1, 0);
                        const int kend = min(w >> 1, NJMAX);
                        float sum = 0.0f;
                        for (int j = jsrt; j <= jend; j++) {
                            const int hp = j - j0 + 1;
                            const int er = (h - 2 * j) * 4;
                            for (int k = ksrt; k <= kend; k++) {
                                const int kp = k - k0 + 1;
                                sum += s_dec[(hp * 16 + kp) * DSTR + er + (w - 2 * k)];
                            }
                        }
                        const int cnt = (jend - jsrt + 1) * (kend - ksrt + 1);
                        const float rcp = (cnt == 4) ? 0.25f : ((cnt == 2) ? 0.5f : 1.0f);
                        outb[(size_t)h * IW + w] = sum * rcp;
                    }
                }
            }
        }
    }
}

extern "C" void kernel_launch(void* const* d_in, const int* in_sizes, int n_in,
                              void* d_out, int out_size) {
    const float* img    = (const float*)d_in[0];
    const float* w_conv = (const float*)d_in[1];
    const float* b_conv = (const float*)d_in[2];
    const float* W_b    = (const float*)d_in[3];
    const float* b_b    = (const float*)d_in[4];
    const float* W_d    = (const float*)d_in[5];
    const float* b_d    = (const float*)d_in[6];
    float* out = (float*)d_out;

    dim3 grid(35, 35, 8);   // 15-patch tiles: ceil(511/15) = 35
    dim3 block(256);
    ae_kernel<<<grid, block>>>(img, w_conv, b_conv, W_b, b_b, W_d, b_d, out);
}

// round 3
// speedup vs baseline: 2.0008x; 1.4252x over previous
#include <cuda_runtime.h>

#define IH 1024
#define IW 1024
#define NJMAX 510          // last valid patch index (nj = nk = 511)
#define TJ 15              // owned patch rows/cols per block
#define DSTR 20            // dec stride in floats (pad: conflict-free LDS/STS.128)

__device__ __forceinline__ float tanhf_fast(float x) {
    float y; asm("tanh.approx.f32 %0, %1;" : "=f"(y) : "f"(x)); return y;
}
// sigmoid(x) = 0.5 + 0.5*tanh(x/2); argument arrives pre-halved via folded weights
__device__ __forceinline__ float sig_from_h(float h) {
    return fmaf(tanhf_fast(h), 0.5f, 0.5f);
}

__global__ __launch_bounds__(256, 5)
void ae_kernel(const float* __restrict__ img,
               const float* __restrict__ w_conv,  // (2,1,2,2)
               const float* __restrict__ b_conv,  // (2,)
               const float* __restrict__ W_b,     // (2,2)
               const float* __restrict__ b_b,     // (2,)
               const float* __restrict__ W_d,     // (2,1,2,2)
               const float* __restrict__ b_d,     // (1,)
               float* __restrict__ out)
{
    // input tile as 17x17 disjoint 2x2 blocks: blk = {x00, x01, x10, x11}
    __shared__ float4 s_blk[17 * 17];          // 4.6 KB
    // dec per patch: 4 groups of 4 (TL,TR,BL,BR quadrant groups), stride 20
    __shared__ float s_dec[256 * DSTR];        // 20 KB

    const int tid = threadIdx.x;
    const int bk = blockIdx.x, bj = blockIdx.y, b = blockIdx.z;

    const int j0 = bj * TJ;
    const int k0 = bk * TJ;
    const int rbase = 2 * j0 - 2;    // input row of halo block row 0 (may be -2)
    const int cbase = 2 * k0 - 2;

    // ---- load 34x34 input halo as 289 2x2 blocks (zero-padded) ----
    const float* imgb = img + (size_t)b * (IH * IW);
    #pragma unroll
    for (int t = tid; t < 289; t += 256) {
        const int J = t / 17;
        const int K = t - J * 17;
        const int gr = rbase + 2 * J;
        const int gc = cbase + 2 * K;
        float2 top = make_float2(0.0f, 0.0f);
        float2 bot = make_float2(0.0f, 0.0f);
        if ((unsigned)gc < 1024u) {     // gc even -> gc+1 in range iff gc is
            const float* p = imgb + (size_t)gr * IW + gc;
            if ((unsigned)gr < 1024u)       top = *(const float2*)(p);
            if ((unsigned)(gr + 1) < 1024u) bot = *(const float2*)(p + IW);
        }
        s_blk[t] = make_float4(top.x, top.y, bot.x, bot.y);
    }

    // ---- tiny weights -> registers ----
    float wc0[4], wc1[4], wd0h[4], wd1h[4];
    #pragma unroll
    for (int i = 0; i < 4; i++) {
        wc0[i]  = __ldg(w_conv + i);
        wc1[i]  = __ldg(w_conv + 4 + i);
        wd0h[i] = __ldg(W_d + i)     * 0.5f;
        wd1h[i] = __ldg(W_d + 4 + i) * 0.5f;
    }
    const float bc0 = __ldg(b_conv + 0), bc1 = __ldg(b_conv + 1);
    const float wb00 = __ldg(W_b + 0), wb01 = __ldg(W_b + 1);
    const float wb10 = __ldg(W_b + 2), wb11 = __ldg(W_b + 3);
    const float bb0 = __ldg(b_b + 0), bb1 = __ldg(b_b + 1);
    const float bdh = __ldg(b_d) * 0.5f;
    const float sconst = sig_from_h(bdh);    // sigmoid(b_d)

    __syncthreads();

    // ================= per-patch pipeline: exactly 1 patch per thread ============
    {
        const int pj = tid >> 4;          // halo patch row 0..15
        const int pk = tid & 15;          // halo patch col 0..15
        const int base = pj * 17 + pk;

        const float4 B00 = s_blk[base];
        const float4 B01 = s_blk[base + 1];
        const float4 B10 = s_blk[base + 17];
        const float4 B11 = s_blk[base + 18];

        float cv0[4], cv1[4];
        #define CONV(e, B) do { \
            float v0 = fmaf(wc0[0], (B).x, fmaf(wc0[1], (B).y, fmaf(wc0[2], (B).z, fmaf(wc0[3], (B).w, bc0)))); \
            float v1 = fmaf(wc1[0], (B).x, fmaf(wc1[1], (B).y, fmaf(wc1[2], (B).z, fmaf(wc1[3], (B).w, bc1)))); \
            cv0[e] = fmaxf(v0, 0.0f); cv1[e] = fmaxf(v1, 0.0f); } while (0)
        CONV(0, B00); CONV(1, B01); CONV(2, B10); CONV(3, B11);
        #undef CONV

        // argmax (first-max semantics: strict >)
        int am0 = 0, am1 = 0;
        float mv0 = cv0[0], mv1 = cv1[0];
        #pragma unroll
        for (int e = 1; e < 4; e++) {
            if (cv0[e] > mv0) { mv0 = cv0[e]; am0 = e; }
            if (cv1[e] > mv1) { mv1 = cv1[e]; am1 = e; }
        }

        // dense + relu
        const float z0 = fmaxf(fmaf(mv0, wb00, fmaf(mv1, wb01, bb0)), 0.0f);
        const float z1 = fmaxf(fmaf(mv0, wb10, fmaf(mv1, wb11, bb1)), 0.0f);
        const float zz1 = (am0 == am1) ? z1 : 0.0f;

        // 8 unconditional sigmoids (1 MUFU each via tanh.approx)
        float4 s0, s1;
        s0.x = sig_from_h(fmaf(z0, wd0h[0], fmaf(zz1, wd1h[0], bdh)));
        s0.y = sig_from_h(fmaf(z0, wd0h[1], fmaf(zz1, wd1h[1], bdh)));
        s0.z = sig_from_h(fmaf(z0, wd0h[2], fmaf(zz1, wd1h[2], bdh)));
        s0.w = sig_from_h(fmaf(z0, wd0h[3], fmaf(zz1, wd1h[3], bdh)));
        s1.x = sig_from_h(fmaf(z1, wd1h[0], bdh));
        s1.y = sig_from_h(fmaf(z1, wd1h[1], bdh));
        s1.z = sig_from_h(fmaf(z1, wd1h[2], bdh));
        s1.w = sig_from_h(fmaf(z1, wd1h[3], bdh));

        // dec tile write: 4 quadrant groups (TL,TR,BL,BR), group g = argmax block g
        float* dp = s_dec + tid * DSTR;
        const float4 sc4 = make_float4(sconst, sconst, sconst, sconst);
        *(float4*)(dp + 0)  = sc4;
        *(float4*)(dp + 4)  = sc4;
        *(float4*)(dp + 8)  = sc4;
        *(float4*)(dp + 12) = sc4;
        *(float4*)(dp + am0 * 4) = s0;                       // same-address order: later wins
        if (am1 != am0) *(float4*)(dp + am1 * 4) = s1;
    }

    __syncthreads();

    // ================= gather: one 2x2 output cell per thread =====================
    float* outb = out + (size_t)b * (IH * IW);
    const int a  = tid >> 4;      // cell row 0..14 (15 invalid)
    const int cb = tid & 15;      // cell col 0..14 (15 invalid)
    const bool interior = (bj >= 1) & (bj <= 33) & (bk >= 1) & (bk <= 33);

    if (a < 15 && cb < 15) {
        if (interior) {
            const float* p00 = s_dec + (a * 16 + cb) * DSTR;   // patch (a,   b)  -> BR group
            const float4 BR = *(const float4*)(p00 + 12);
            const float4 BL = *(const float4*)(p00 + DSTR + 8);        // (a, b+1)
            const float4 TR = *(const float4*)(p00 + 16 * DSTR + 4);   // (a+1, b)
            const float4 TL = *(const float4*)(p00 + 17 * DSTR + 0);   // (a+1, b+1)

            const float pix00 = (BR.x + BL.x) + (TR.x + TL.x);
            const float pix01 = (BR.y + BL.y) + (TR.y + TL.y);
            const float pix10 = (BR.z + BL.z) + (TR.z + TL.z);
            const float pix11 = (BR.w + BL.w) + (TR.w + TL.w);

            const int h = 2 * j0 + 2 * a;
            const int w = 2 * k0 + 2 * cb;
            *(float2*)&outb[(size_t)h * IW + w]       = make_float2(pix00 * 0.25f, pix01 * 0.25f);
            *(float2*)&outb[(size_t)(h + 1) * IW + w] = make_float2(pix10 * 0.25f, pix11 * 0.25f);
        } else {
            #pragma unroll
            for (int di = 0; di < 2; di++) {
                #pragma unroll
                for (int dj = 0; dj < 2; dj++) {
                    const int h = 2 * j0 + 2 * a + di;
                    const int w = 2 * k0 + 2 * cb + dj;
                    if (h < IH && w < IW) {
                        const int jsrt = max((h - 2) >> 1, 0);
                        const int jend = min(h >> 1, NJMAX);
                        const int ksrt = max((w - 2) >> 1, 0);
                        const int kend = min(w >> 1, NJMAX);
                        float sum = 0.0f;
                        for (int j = jsrt; j <= jend; j++) {
                            const int hp = j - j0 + 1;
                            const int row = h - 2 * j;
                            for (int k = ksrt; k <= kend; k++) {
                                const int kp = k - k0 + 1;
                                const int col = w - 2 * k;
                                const int off = ((row >> 1) * 2 + (col >> 1)) * 4
                                              + (row & 1) * 2 + (col & 1);
                                sum += s_dec[(hp * 16 + kp) * DSTR + off];
                            }
                        }
                        const int cnt = (jend - jsrt + 1) * (kend - ksrt + 1);
                        const float rcp = (cnt == 4) ? 0.25f : ((cnt == 2) ? 0.5f : 1.0f);
                        outb[(size_t)h * IW + w] = sum * rcp;
                    }
                }
            }
        }
    }
}

extern "C" void kernel_launch(void* const* d_in, const int* in_sizes, int n_in,
                              void* d_out, int out_size) {
    const float* img    = (const float*)d_in[0];
    const float* w_conv = (const float*)d_in[1];
    const float* b_conv = (const float*)d_in[2];
    const float* W_b    = (const float*)d_in[3];
    const float* b_b    = (const float*)d_in[4];
    const float* W_d    = (const float*)d_in[5];
    const float* b_d    = (const float*)d_in[6];
    float* out = (float*)d_out;

    dim3 grid(35, 35, 8);   // 15-patch tiles: ceil(511/15) = 35
    dim3 block(256);
    ae_kernel<<<grid, block>>>(img, w_conv, b_conv, W_b, b_b, W_d, b_d, out);
}

// round 4
// speedup vs baseline: 2.0808x; 1.0400x over previous
#include <cuda_runtime.h>

#define IH 1024
#define IW 1024
#define TJ 15              // owned cell rows/cols per block (15x15 cells = 30x30 px)
#define BROWS 18           // halo 2x2-block rows in smem
#define BCOLS 17           // halo 2x2-block cols in smem

__device__ __forceinline__ float tanhf_fast(float x) {
    float y; asm("tanh.approx.f32 %0, %1;" : "=f"(y) : "f"(x)); return y;
}

// conv(2ch) -> relu -> argmax(first-max) -> dense -> relu ; blocks A,B,C,D = TL,TR,BL,BR
__device__ __forceinline__ void patch_fw(
    const float4 A, const float4 Bb, const float4 C, const float4 D,
    const float* wc0, const float* wc1, float bc0, float bc1,
    float wb00, float wb01, float wb10, float wb11, float bb0, float bb1,
    float& z0, float& z1, int& am0, int& am1)
{
    float cv0[4], cv1[4];
#define CONVB(e, B) do { \
        float v0 = fmaf(wc0[0], (B).x, fmaf(wc0[1], (B).y, fmaf(wc0[2], (B).z, fmaf(wc0[3], (B).w, bc0)))); \
        float v1 = fmaf(wc1[0], (B).x, fmaf(wc1[1], (B).y, fmaf(wc1[2], (B).z, fmaf(wc1[3], (B).w, bc1)))); \
        cv0[e] = fmaxf(v0, 0.0f); cv1[e] = fmaxf(v1, 0.0f); } while (0)
    CONVB(0, A); CONVB(1, Bb); CONVB(2, C); CONVB(3, D);
#undef CONVB
    am0 = 0; am1 = 0;
    float mv0 = cv0[0], mv1 = cv1[0];
#pragma unroll
    for (int e = 1; e < 4; e++) {
        if (cv0[e] > mv0) { mv0 = cv0[e]; am0 = e; }
        if (cv1[e] > mv1) { mv1 = cv1[e]; am1 = e; }
    }
    z0 = fmaxf(fmaf(mv0, wb00, fmaf(mv1, wb01, bb0)), 0.0f);
    z1 = fmaxf(fmaf(mv0, wb10, fmaf(mv1, wb11, bb1)), 0.0f);
}

// quadrant group g of a patch, pre-scaled by hf = 0.5 * patch_valid
// value[pq] = valid * sigmoid(t0*Wd0[pq] + t1*Wd1[pq] + bd), sigmoid via tanh
__device__ __forceinline__ float4 group4(
    float z0, float z1, int am0, int am1, int g, float hf,
    const float* wd0h, const float* wd1h, float bdh)
{
    const float t0 = (am0 == g) ? z0 : 0.0f;
    const float t1 = (am1 == g) ? z1 : 0.0f;
    float4 r;
    r.x = fmaf(tanhf_fast(fmaf(t0, wd0h[0], fmaf(t1, wd1h[0], bdh))), hf, hf);
    r.y = fmaf(tanhf_fast(fmaf(t0, wd0h[1], fmaf(t1, wd1h[1], bdh))), hf, hf);
    r.z = fmaf(tanhf_fast(fmaf(t0, wd0h[2], fmaf(t1, wd1h[2], bdh))), hf, hf);
    r.w = fmaf(tanhf_fast(fmaf(t0, wd0h[3], fmaf(t1, wd1h[3], bdh))), hf, hf);
    return r;
}

__global__ __launch_bounds__(256, 3)
void ae_kernel(const float* __restrict__ img,
               const float* __restrict__ w_conv,  // (2,1,2,2)
               const float* __restrict__ b_conv,  // (2,)
               const float* __restrict__ W_b,     // (2,2)
               const float* __restrict__ b_b,     // (2,)
               const float* __restrict__ W_d,     // (2,1,2,2)
               const float* __restrict__ b_d,     // (1,)
               float* __restrict__ out)
{
    // input halo as disjoint 2x2 pixel blocks: {x00,x01,x10,x11}
    __shared__ float4 s_blk[BROWS * BCOLS];   // 306 * 16B = 4.9 KB

    const int tid = threadIdx.x;
    const int a  = tid >> 4;      // cell row 0..15 (15 = donor-only)
    const int cb = tid & 15;      // cell col 0..15 (15 = donor-only)
    const int bk = blockIdx.x, bj = blockIdx.y, b = blockIdx.z;

    const int j0 = bj * TJ;
    const int k0 = bk * TJ;
    const int rbase = 2 * j0 - 2;   // pixel row of block row 0
    const int cbase = 2 * k0 - 2;

    // ---- stage 18x17 block tile (36x34 pixels), zero-padded ----
    const float* imgb = img + (size_t)b * (IH * IW);
#pragma unroll
    for (int t = tid; t < BROWS * BCOLS; t += 256) {
        const int R = t / BCOLS;
        const int C = t - R * BCOLS;
        const int gr = rbase + 2 * R;
        const int gc = cbase + 2 * C;
        float2 top = make_float2(0.0f, 0.0f);
        float2 bot = make_float2(0.0f, 0.0f);
        if ((unsigned)gc < 1024u) {
            const float* p = imgb + (size_t)gr * IW + gc;
            if ((unsigned)gr < 1024u)       top = *(const float2*)(p);
            if ((unsigned)(gr + 1) < 1024u) bot = *(const float2*)(p + IW);
        }
        s_blk[t] = make_float4(top.x, top.y, bot.x, bot.y);
    }

    // ---- tiny weights -> registers ----
    float wc0[4], wc1[4], wd0h[4], wd1h[4];
#pragma unroll
    for (int i = 0; i < 4; i++) {
        wc0[i]  = __ldg(w_conv + i);
        wc1[i]  = __ldg(w_conv + 4 + i);
        wd0h[i] = __ldg(W_d + i)     * 0.5f;
        wd1h[i] = __ldg(W_d + 4 + i) * 0.5f;
    }
    const float bc0 = __ldg(b_conv + 0), bc1 = __ldg(b_conv + 1);
    const float wb00 = __ldg(W_b + 0), wb01 = __ldg(W_b + 1);
    const float wb10 = __ldg(W_b + 2), wb11 = __ldg(W_b + 3);
    const float bb0 = __ldg(b_b + 0), bb1 = __ldg(b_b + 1);
    const float bdh = __ldg(b_d) * 0.5f;

    __syncthreads();

    // ---- this thread's two patches: P1 = (j0+a-1, k0+cb-1), P2 = (j0+a, k0+cb-1) ----
    const int jr1 = j0 + a - 1;
    const int jr2 = j0 + a;
    const int kc  = k0 + cb - 1;
    const bool vj1 = (unsigned)jr1 <= 510u;
    const bool vj2 = (unsigned)jr2 <= 510u;
    const bool vk  = (unsigned)kc  <= 510u;
    const bool vkn = (unsigned)(kc + 1) <= 510u;

    const int base = a * BCOLS + cb;
    const float4 B00 = s_blk[base];
    const float4 B01 = s_blk[base + 1];
    const float4 B10 = s_blk[base + BCOLS];
    const float4 B11 = s_blk[base + BCOLS + 1];
    const float4 B20 = s_blk[base + 2 * BCOLS];
    const float4 B21 = s_blk[base + 2 * BCOLS + 1];

    float z0a, z1a, z0b, z1b;
    int am0a, am1a, am0b, am1b;
    patch_fw(B00, B01, B10, B11, wc0, wc1, bc0, bc1,
             wb00, wb01, wb10, wb11, bb0, bb1, z0a, z1a, am0a, am1a);
    patch_fw(B10, B11, B20, B21, wc0, wc1, bc0, bc1,
             wb00, wb01, wb10, wb11, bb0, bb1, z0b, z1b, am0b, am1b);

    const float hf1 = (vj1 && vk) ? 0.5f : 0.0f;
    const float hf2 = (vj2 && vk) ? 0.5f : 0.0f;

    // self-needed groups: BR (g=3) of P1, TR (g=1) of P2
    const float4 sBR = group4(z0a, z1a, am0a, am1a, 3, hf1, wd0h, wd1h, bdh);
    const float4 sTR = group4(z0b, z1b, am0b, am1b, 1, hf2, wd0h, wd1h, bdh);
    // donated groups: BL (g=2) of P1, TL (g=0) of P2 -> to lane-1
    const float4 dBL = group4(z0a, z1a, am0a, am1a, 2, hf1, wd0h, wd1h, bdh);
    const float4 dTL = group4(z0b, z1b, am0b, am1b, 0, hf2, wd0h, wd1h, bdh);

    float4 nBL, nTL;
    nBL.x = __shfl_down_sync(0xffffffffu, dBL.x, 1);
    nBL.y = __shfl_down_sync(0xffffffffu, dBL.y, 1);
    nBL.z = __shfl_down_sync(0xffffffffu, dBL.z, 1);
    nBL.w = __shfl_down_sync(0xffffffffu, dBL.w, 1);
    nTL.x = __shfl_down_sync(0xffffffffu, dTL.x, 1);
    nTL.y = __shfl_down_sync(0xffffffffu, dTL.y, 1);
    nTL.z = __shfl_down_sync(0xffffffffu, dTL.z, 1);
    nTL.w = __shfl_down_sync(0xffffffffu, dTL.w, 1);

    // ---- combine + store ----
    const int h = 2 * (j0 + a);
    const int w = 2 * (k0 + cb);
    if (a < 15 && cb < 15 && h < IH && w < IW) {
        const float pix00 = (sBR.x + nBL.x) + (sTR.x + nTL.x);
        const float pix01 = (sBR.y + nBL.y) + (sTR.y + nTL.y);
        const float pix10 = (sBR.z + nBL.z) + (sTR.z + nTL.z);
        const float pix11 = (sBR.w + nBL.w) + (sTR.w + nTL.w);

        const int cnt = ((int)vj1 + (int)vj2) * ((int)vk + (int)vkn);
        const float rcp = (cnt == 4) ? 0.25f : ((cnt == 2) ? 0.5f : 1.0f);

        float* outb = out + (size_t)b * (IH * IW);
        *(float2*)&outb[(size_t)h * IW + w]       = make_float2(pix00 * rcp, pix01 * rcp);
        *(float2*)&outb[(size_t)(h + 1) * IW + w] = make_float2(pix10 * rcp, pix11 * rcp);
    }
}

extern "C" void kernel_launch(void* const* d_in, const int* in_sizes, int n_in,
                              void* d_out, int out_size) {
    const float* img    = (const float*)d_in[0];
    const float* w_conv = (const float*)d_in[1];
    const float* b_conv = (const float*)d_in[2];
    const float* W_b    = (const float*)d_in[3];
    const float* b_b    = (const float*)d_in[4];
    const float* W_d    = (const float*)d_in[5];
    const float* b_d    = (const float*)d_in[6];
    float* out = (float*)d_out;

    dim3 grid(35, 35, 8);   // ceil(512/15) cells per dim
    dim3 block(256);
    ae_kernel<<<grid, block>>>(img, w_conv, b_conv, W_b, b_b, W_d, b_d, out);
}

// round 5
// speedup vs baseline: 2.2185x; 1.0662x over previous
#include <cuda_runtime.h>

#define IH 1024
#define IW 1024
#define TJ 15              // owned cell rows/cols per block (15x15 cells = 30x30 px)
#define BDIM 17            // halo 2x2-block rows/cols in smem (17x17)

__device__ __forceinline__ float tanhf_fast(float x) {
    float y; asm("tanh.approx.f32 %0, %1;" : "=f"(y) : "f"(x)); return y;
}

// quadrant group g of the patch, pre-scaled by hf = 0.5 * patch_valid
// value[pq] = valid * sigmoid(t0*Wd0[pq] + t1*Wd1[pq] + bd), sigmoid(x)=0.5+0.5*tanh(x/2)
__device__ __forceinline__ float4 group4(
    float z0, float z1, int am0, int am1, int g, float hf,
    const float4 wd0h, const float4 wd1h, float bdh)
{
    const float t0 = (am0 == g) ? z0 : 0.0f;
    const float t1 = (am1 == g) ? z1 : 0.0f;
    float4 r;
    r.x = fmaf(tanhf_fast(fmaf(t0, wd0h.x, fmaf(t1, wd1h.x, bdh))), hf, hf);
    r.y = fmaf(tanhf_fast(fmaf(t0, wd0h.y, fmaf(t1, wd1h.y, bdh))), hf, hf);
    r.z = fmaf(tanhf_fast(fmaf(t0, wd0h.z, fmaf(t1, wd1h.z, bdh))), hf, hf);
    r.w = fmaf(tanhf_fast(fmaf(t0, wd0h.w, fmaf(t1, wd1h.w, bdh))), hf, hf);
    return r;
}

__global__ __launch_bounds__(256, 4)
void ae_kernel(const float* __restrict__ img,
               const float* __restrict__ w_conv,  // (2,1,2,2)
               const float* __restrict__ b_conv,  // (2,)
               const float* __restrict__ W_b,     // (2,2)
               const float* __restrict__ b_b,     // (2,)
               const float* __restrict__ W_d,     // (2,1,2,2)
               const float* __restrict__ b_d,     // (1,)
               float* __restrict__ out)
{
    // input halo as disjoint 2x2 pixel blocks: {x00,x01,x10,x11}
    __shared__ float4 s_blk[BDIM * BDIM];   // 289 * 16B = 4.6 KB
    __shared__ float4 s_tr[256];            // TR group of each thread's patch (4 KB)
    __shared__ float4 s_tl[256];            // TL group (4 KB)

    const int tid = threadIdx.x;
    const int a  = tid >> 4;      // patch/cell row 0..15 (cell 15 = donor-only)
    const int cb = tid & 15;      // patch/cell col 0..15 (cell 15 = donor-only)
    const int bk = blockIdx.x, bj = blockIdx.y, b = blockIdx.z;

    const int j0 = bj * TJ;
    const int k0 = bk * TJ;
    const int rbase = 2 * j0 - 2;   // pixel row of block row 0
    const int cbase = 2 * k0 - 2;

    // ---- stage 17x17 block tile (34x34 pixels), zero-padded ----
    const float* imgb = img + (size_t)b * (IH * IW);
#pragma unroll
    for (int t = tid; t < BDIM * BDIM; t += 256) {
        const int R = t / BDIM;
        const int C = t - R * BDIM;
        const int gr = rbase + 2 * R;
        const int gc = cbase + 2 * C;
        float2 top = make_float2(0.0f, 0.0f);
        float2 bot = make_float2(0.0f, 0.0f);
        if ((unsigned)gc < 1024u) {          // gc even -> gc+1 in range iff gc is
            const float* p = imgb + (size_t)gr * IW + gc;
            if ((unsigned)gr < 1024u)       top = *(const float2*)(p);
            if ((unsigned)(gr + 1) < 1024u) bot = *(const float2*)(p + IW);
        }
        s_blk[t] = make_float4(top.x, top.y, bot.x, bot.y);
    }

    // ---- tiny weights -> registers (vector loads, uniform) ----
    const float4 wc0 = __ldg((const float4*)w_conv);
    const float4 wc1 = __ldg((const float4*)(w_conv + 4));
    const float2 bc  = __ldg((const float2*)b_conv);
    const float4 wb  = __ldg((const float4*)W_b);        // wb00,wb01,wb10,wb11
    const float2 bb  = __ldg((const float2*)b_b);
    float4 wd0h = __ldg((const float4*)W_d);
    float4 wd1h = __ldg((const float4*)(W_d + 4));
    wd0h.x *= 0.5f; wd0h.y *= 0.5f; wd0h.z *= 0.5f; wd0h.w *= 0.5f;
    wd1h.x *= 0.5f; wd1h.y *= 0.5f; wd1h.z *= 0.5f; wd1h.w *= 0.5f;
    const float bdh = __ldg(b_d) * 0.5f;

    __syncthreads();

    // ---- this thread's single patch: (j0+a-1, k0+cb-1) ----
    const int jr = j0 + a - 1;
    const int kc = k0 + cb - 1;
    const float hf = ((unsigned)jr <= 510u && (unsigned)kc <= 510u) ? 0.5f : 0.0f;

    const int base = a * BDIM + cb;
    const float4 A = s_blk[base];
    const float4 Bq = s_blk[base + 1];
    const float4 C = s_blk[base + BDIM];
    const float4 D = s_blk[base + BDIM + 1];

    // conv(2ch) -> relu
    float cv0[4], cv1[4];
#define CONVB(e, B) do { \
        float v0 = fmaf(wc0.x, (B).x, fmaf(wc0.y, (B).y, fmaf(wc0.z, (B).z, fmaf(wc0.w, (B).w, bc.x)))); \
        float v1 = fmaf(wc1.x, (B).x, fmaf(wc1.y, (B).y, fmaf(wc1.z, (B).z, fmaf(wc1.w, (B).w, bc.y)))); \
        cv0[e] = fmaxf(v0, 0.0f); cv1[e] = fmaxf(v1, 0.0f); } while (0)
    CONVB(0, A); CONVB(1, Bq); CONVB(2, C); CONVB(3, D);
#undef CONVB

    // argmax (first-max semantics: strict >)
    int am0 = 0, am1 = 0;
    float mv0 = cv0[0], mv1 = cv1[0];
#pragma unroll
    for (int e = 1; e < 4; e++) {
        if (cv0[e] > mv0) { mv0 = cv0[e]; am0 = e; }
        if (cv1[e] > mv1) { mv1 = cv1[e]; am1 = e; }
    }

    // dense + relu
    const float z0 = fmaxf(fmaf(mv0, wb.x, fmaf(mv1, wb.y, bb.x)), 0.0f);
    const float z1 = fmaxf(fmaf(mv0, wb.z, fmaf(mv1, wb.w, bb.y)), 0.0f);

    // 4 quadrant groups (16 sigmoids), each pre-scaled by validity
    const float4 gBR = group4(z0, z1, am0, am1, 3, hf, wd0h, wd1h, bdh);  // -> own cell
    const float4 gBL = group4(z0, z1, am0, am1, 2, hf, wd0h, wd1h, bdh);  // -> left cell (shfl)
    const float4 gTR = group4(z0, z1, am0, am1, 1, hf, wd0h, wd1h, bdh);  // -> cell above (smem)
    const float4 gTL = group4(z0, z1, am0, am1, 0, hf, wd0h, wd1h, bdh);  // -> cell above-left (smem)

    s_tr[tid] = gTR;
    s_tl[tid] = gTL;

    // BL of right-neighbor patch (lane+1 within warp; cb=15 consumers are invalid anyway)
    float4 nBL;
    nBL.x = __shfl_down_sync(0xffffffffu, gBL.x, 1);
    nBL.y = __shfl_down_sync(0xffffffffu, gBL.y, 1);
    nBL.z = __shfl_down_sync(0xffffffffu, gBL.z, 1);
    nBL.w = __shfl_down_sync(0xffffffffu, gBL.w, 1);

    __syncthreads();

    // ---- gather + store: cell (a,cb), output pixels (2(j0+a), 2(k0+cb)) ----
    const int h = 2 * (j0 + a);
    const int w = 2 * (k0 + cb);
    if (a < 15 && cb < 15 && h < IH && w < IW) {
        const float4 vTR = s_tr[tid + 16];      // patch (a+1, cb)
        const float4 vTL = s_tl[tid + 17];      // patch (a+1, cb+1)

        const float pix00 = (gBR.x + nBL.x) + (vTR.x + vTL.x);
        const float pix01 = (gBR.y + nBL.y) + (vTR.y + vTL.y);
        const float pix10 = (gBR.z + nBL.z) + (vTR.z + vTL.z);
        const float pix11 = (gBR.w + nBL.w) + (vTR.w + vTL.w);

        const bool vj1 = (unsigned)(j0 + a - 1) <= 510u;
        const bool vj2 = (unsigned)(j0 + a)     <= 510u;
        const bool vk  = (unsigned)(k0 + cb - 1) <= 510u;
        const bool vkn = (unsigned)(k0 + cb)     <= 510u;
        const int cnt = ((int)vj1 + (int)vj2) * ((int)vk + (int)vkn);
        const float rcp = (cnt == 4) ? 0.25f : ((cnt == 2) ? 0.5f : 1.0f);

        float* outb = out + (size_t)b * (IH * IW);
        *(float2*)&outb[(size_t)h * IW + w]       = make_float2(pix00 * rcp, pix01 * rcp);
        *(float2*)&outb[(size_t)(h + 1) * IW + w] = make_float2(pix10 * rcp, pix11 * rcp);
    }
}

extern "C" void kernel_launch(void* const* d_in, const int* in_sizes, int n_in,
                              void* d_out, int out_size) {
    const float* img    = (const float*)d_in[0];
    const float* w_conv = (const float*)d_in[1];
    const float* b_conv = (const float*)d_in[2];
    const float* W_b    = (const float*)d_in[3];
    const float* b_b    = (const float*)d_in[4];
    const float* W_d    = (const float*)d_in[5];
    const float* b_d    = (const float*)d_in[6];
    float* out = (float*)d_out;

    dim3 grid(35, 35, 8);   // ceil(512/15) cells per dim
    dim3 block(256);
    ae_kernel<<<grid, block>>>(img, w_conv, b_conv, W_b, b_b, W_d, b_d, out);
}

// round 6
// speedup vs baseline: 2.6397x; 1.1899x over previous
#include <cuda_runtime.h>

#define IH 1024
#define IW 1024
#define TJ 15              // owned cell rows/cols per block (15x15 cells = 30x30 px)
#define BDIM 17            // halo 2x2-block rows/cols in smem (17x17)

__device__ __forceinline__ float tanhf_fast(float x) {
    float y; asm("tanh.approx.f32 %0, %1;" : "=f"(y) : "f"(x)); return y;
}

__global__ __launch_bounds__(256, 4)
void ae_kernel(const float* __restrict__ img,
               const float* __restrict__ w_conv,  // (2,1,2,2)
               const float* __restrict__ b_conv,  // (2,)
               const float* __restrict__ W_b,     // (2,2)
               const float* __restrict__ b_b,     // (2,)
               const float* __restrict__ W_d,     // (2,1,2,2)
               const float* __restrict__ b_d,     // (1,)
               float* __restrict__ out)
{
    // input halo as disjoint 2x2 pixel blocks: {x00,x01,x10,x11}
    __shared__ float4 s_blk[BDIM * BDIM];   // 4.6 KB
    __shared__ float4 s_tr[256];            // TR group of each thread's patch
    __shared__ float4 s_tl[256];            // TL group

    const int tid = threadIdx.x;
    const int a  = tid >> 4;      // patch/cell row 0..15 (cell 15 = donor-only)
    const int cb = tid & 15;      // patch/cell col 0..15 (cell 15 = donor-only)
    const int bk = blockIdx.x, bj = blockIdx.y, bz = blockIdx.z;

    const int j0 = bj * TJ;
    const int k0 = bk * TJ;
    const int rbase = 2 * j0 - 2;   // pixel row of block row 0
    const int cbase = 2 * k0 - 2;

    // ---- tiny weights -> registers (vector loads, uniform, hoisted across both images) ----
    const float4 wc0 = __ldg((const float4*)w_conv);
    const float4 wc1 = __ldg((const float4*)(w_conv + 4));
    const float2 bc  = __ldg((const float2*)b_conv);
    const float4 wb  = __ldg((const float4*)W_b);
    const float2 bb  = __ldg((const float2*)b_b);
    float wd0h[4], wd1h[4];
    {
        const float4 t0 = __ldg((const float4*)W_d);
        const float4 t1 = __ldg((const float4*)(W_d + 4));
        wd0h[0] = t0.x * 0.5f; wd0h[1] = t0.y * 0.5f; wd0h[2] = t0.z * 0.5f; wd0h[3] = t0.w * 0.5f;
        wd1h[0] = t1.x * 0.5f; wd1h[1] = t1.y * 0.5f; wd1h[2] = t1.z * 0.5f; wd1h[3] = t1.w * 0.5f;
    }
    const float bdh = __ldg(b_d) * 0.5f;
    const float thc = tanhf_fast(bdh);      // tanh for inactive quadrants (uniform)

    // ---- per-thread constants (hoisted across both images) ----
    const int jr = j0 + a - 1;              // this thread's patch row
    const int kc = k0 + cb - 1;             // this thread's patch col
    const float hf = ((unsigned)jr <= 510u && (unsigned)kc <= 510u) ? 0.5f : 0.0f;

    const int h = 2 * (j0 + a);
    const int w = 2 * (k0 + cb);
    const bool cell_ok = (a < 15) & (cb < 15) & (h < IH) & (w < IW);
    const bool vj1 = (unsigned)jr        <= 510u;
    const bool vj2 = (unsigned)(jr + 1)  <= 510u;
    const bool vk  = (unsigned)kc        <= 510u;
    const bool vkn = (unsigned)(kc + 1)  <= 510u;
    const int cnt = ((int)vj1 + (int)vj2) * ((int)vk + (int)vkn);
    const float rcp = (cnt == 4) ? 0.25f : ((cnt == 2) ? 0.5f : 1.0f);

    const int sbase = a * BDIM + cb;

#pragma unroll
    for (int ib = 0; ib < 2; ib++) {
        const int b = 2 * bz + ib;
        const float* imgb = img + (size_t)b * (IH * IW);

        // ---- stage 17x17 block tile (34x34 pixels), zero-padded ----
#pragma unroll
        for (int t = tid; t < BDIM * BDIM; t += 256) {
            const int R = t / BDIM;
            const int C = t - R * BDIM;
            const int gr = rbase + 2 * R;
            const int gc = cbase + 2 * C;
            float2 top = make_float2(0.0f, 0.0f);
            float2 bot = make_float2(0.0f, 0.0f);
            if ((unsigned)gc < 1024u) {
                const float* p = imgb + (size_t)gr * IW + gc;
                if ((unsigned)gr < 1024u)       top = *(const float2*)(p);
                if ((unsigned)(gr + 1) < 1024u) bot = *(const float2*)(p + IW);
            }
            s_blk[t] = make_float4(top.x, top.y, bot.x, bot.y);
        }
        __syncthreads();

        // ---- this thread's single patch ----
        const float4 A  = s_blk[sbase];
        const float4 Bq = s_blk[sbase + 1];
        const float4 C  = s_blk[sbase + BDIM];
        const float4 D  = s_blk[sbase + BDIM + 1];

        // conv(2ch) -> relu
        float cv0[4], cv1[4];
#define CONVB(e, B) do { \
        float v0 = fmaf(wc0.x, (B).x, fmaf(wc0.y, (B).y, fmaf(wc0.z, (B).z, fmaf(wc0.w, (B).w, bc.x)))); \
        float v1 = fmaf(wc1.x, (B).x, fmaf(wc1.y, (B).y, fmaf(wc1.z, (B).z, fmaf(wc1.w, (B).w, bc.y)))); \
        cv0[e] = fmaxf(v0, 0.0f); cv1[e] = fmaxf(v1, 0.0f); } while (0)
        CONVB(0, A); CONVB(1, Bq); CONVB(2, C); CONVB(3, D);
#undef CONVB

        // argmax (first-max semantics: strict >)
        int am0 = 0, am1 = 0;
        float mv0 = cv0[0], mv1 = cv1[0];
#pragma unroll
        for (int e = 1; e < 4; e++) {
            if (cv0[e] > mv0) { mv0 = cv0[e]; am0 = e; }
            if (cv1[e] > mv1) { mv1 = cv1[e]; am1 = e; }
        }

        // dense + relu
        const float z0 = fmaxf(fmaf(mv0, wb.x, fmaf(mv1, wb.y, bb.x)), 0.0f);
        const float z1 = fmaxf(fmaf(mv0, wb.z, fmaf(mv1, wb.w, bb.y)), 0.0f);
        const float zz1 = (am0 == am1) ? z1 : 0.0f;

        // only 8 live tanh evaluations; inactive quadrants use thc
        float th0[4], th1[4];
#pragma unroll
        for (int pq = 0; pq < 4; pq++) {
            th0[pq] = tanhf_fast(fmaf(z0, wd0h[pq], fmaf(zz1, wd1h[pq], bdh)));
            th1[pq] = tanhf_fast(fmaf(z1, wd1h[pq], bdh));
        }

        // build the 4 quadrant groups via select; value = hf*(tanh+1) = fma(tanh,hf,hf)
        float4 grp[4];
#pragma unroll
        for (int g = 0; g < 4; g++) {
            const bool p0 = (am0 == g);
            const bool p1 = (am1 == g);
            float4 r;
            r.x = fmaf(p0 ? th0[0] : (p1 ? th1[0] : thc), hf, hf);
            r.y = fmaf(p0 ? th0[1] : (p1 ? th1[1] : thc), hf, hf);
            r.z = fmaf(p0 ? th0[2] : (p1 ? th1[2] : thc), hf, hf);
            r.w = fmaf(p0 ? th0[3] : (p1 ? th1[3] : thc), hf, hf);
            grp[g] = r;
        }
        const float4 gTL = grp[0];   // -> cell above-left (smem)
        const float4 gTR = grp[1];   // -> cell above (smem)
        const float4 gBL = grp[2];   // -> left cell (shfl)
        const float4 gBR = grp[3];   // -> own cell (regs)

        s_tr[tid] = gTR;
        s_tl[tid] = gTL;

        float4 nBL;
        nBL.x = __shfl_down_sync(0xffffffffu, gBL.x, 1);
        nBL.y = __shfl_down_sync(0xffffffffu, gBL.y, 1);
        nBL.z = __shfl_down_sync(0xffffffffu, gBL.z, 1);
        nBL.w = __shfl_down_sync(0xffffffffu, gBL.w, 1);

        __syncthreads();

        // ---- gather + store ----
        if (cell_ok) {
            const float4 vTR = s_tr[tid + 16];      // patch (a+1, cb)
            const float4 vTL = s_tl[tid + 17];      // patch (a+1, cb+1)

            const float pix00 = (gBR.x + nBL.x) + (vTR.x + vTL.x);
            const float pix01 = (gBR.y + nBL.y) + (vTR.y + vTL.y);
            const float pix10 = (gBR.z + nBL.z) + (vTR.z + vTL.z);
            const float pix11 = (gBR.w + nBL.w) + (vTR.w + vTL.w);

            float* outb = out + (size_t)b * (IH * IW);
            *(float2*)&outb[(size_t)h * IW + w]       = make_float2(pix00 * rcp, pix01 * rcp);
            *(float2*)&outb[(size_t)(h + 1) * IW + w] = make_float2(pix10 * rcp, pix11 * rcp);
        }
    }
}

extern "C" void kernel_launch(void* const* d_in, const int* in_sizes, int n_in,
                              void* d_out, int out_size) {
    const float* img    = (const float*)d_in[0];
    const float* w_conv = (const float*)d_in[1];
    const float* b_conv = (const float*)d_in[2];
    const float* W_b    = (const float*)d_in[3];
    const float* b_b    = (const float*)d_in[4];
    const float* W_d    = (const float*)d_in[5];
    const float* b_d    = (const float*)d_in[6];
    float* out = (float*)d_out;

    dim3 grid(35, 35, 4);   // ceil(512/15) cells per dim; 2 images per block
    dim3 block(256);
    ae_kernel<<<grid, block>>>(img, w_conv, b_conv, W_b, b_b, W_d, b_d, out);
}

// round 7
// speedup vs baseline: 2.8620x; 1.0842x over previous
#include <cuda_runtime.h>

#define IH 1024
#define IW 1024
#define TJ 15              // owned cell rows/cols per block (15x15 cells = 30x30 px)
#define BDIM 17            // halo 2x2-block rows/cols in smem (17x17)
#define IMGS_PER_BLOCK 4

__device__ __forceinline__ float tanhf_fast(float x) {
    float y; asm("tanh.approx.f32 %0, %1;" : "=f"(y) : "f"(x)); return y;
}

__global__ __launch_bounds__(256, 4)
void ae_kernel(const float* __restrict__ img,
               const float* __restrict__ w_conv,  // (2,1,2,2)
               const float* __restrict__ b_conv,  // (2,)
               const float* __restrict__ W_b,     // (2,2)
               const float* __restrict__ b_b,     // (2,)
               const float* __restrict__ W_d,     // (2,1,2,2)
               const float* __restrict__ b_d,     // (1,)
               float* __restrict__ out)
{
    // input halo as disjoint 2x2 pixel blocks: {x00,x01,x10,x11}
    __shared__ float4 s_blk[BDIM * BDIM];   // 4.6 KB
    __shared__ float4 s_top[256];           // combined (TR + right-neighbor TL) per producer

    const int tid = threadIdx.x;
    const int a  = tid >> 4;      // patch/cell row 0..15
    const int cb = tid & 15;      // patch/cell col 0..15
    const int bk = blockIdx.x, bj = blockIdx.y, bz = blockIdx.z;

    const int j0 = bj * TJ;
    const int k0 = bk * TJ;
    const int rbase = 2 * j0 - 2;   // pixel row of block row 0
    const int cbase = 2 * k0 - 2;

    // ---- tiny weights -> registers (uniform, hoisted across all images) ----
    const float4 wc0 = __ldg((const float4*)w_conv);
    const float4 wc1 = __ldg((const float4*)(w_conv + 4));
    const float2 bc  = __ldg((const float2*)b_conv);
    const float4 wb  = __ldg((const float4*)W_b);
    const float2 bb  = __ldg((const float2*)b_b);
    float wd0h[4], wd1h[4];
    {
        const float4 t0 = __ldg((const float4*)W_d);
        const float4 t1 = __ldg((const float4*)(W_d + 4));
        wd0h[0] = t0.x * 0.5f; wd0h[1] = t0.y * 0.5f; wd0h[2] = t0.z * 0.5f; wd0h[3] = t0.w * 0.5f;
        wd1h[0] = t1.x * 0.5f; wd1h[1] = t1.y * 0.5f; wd1h[2] = t1.z * 0.5f; wd1h[3] = t1.w * 0.5f;
    }
    const float bdh = __ldg(b_d) * 0.5f;
    const float thc = tanhf_fast(bdh);      // tanh for inactive quadrants (uniform)

    // ---- per-thread constants (hoisted) ----
    const int jr = j0 + a - 1;              // this thread's patch row
    const int kc = k0 + cb - 1;             // this thread's patch col
    const float hf = ((unsigned)jr <= 510u && (unsigned)kc <= 510u) ? 0.5f : 0.0f;
    const float hfc = fmaf(thc, hf, hf);    // constant quadrant value, pre-scaled

    const int h = 2 * (j0 + a);
    const int w = 2 * (k0 + cb);
    const bool cell_ok = (a < 15) & (cb < 15) & (h < IH) & (w < IW);
    const bool vj1 = (unsigned)jr        <= 510u;
    const bool vj2 = (unsigned)(jr + 1)  <= 510u;
    const bool vk  = (unsigned)kc        <= 510u;
    const bool vkn = (unsigned)(kc + 1)  <= 510u;
    const int cnt = ((int)vj1 + (int)vj2) * ((int)vk + (int)vkn);
    const float rcp = (cnt == 4) ? 0.25f : ((cnt == 2) ? 0.5f : 1.0f);

    const int sbase = a * BDIM + cb;

    // ---- staging addressing (image-invariant, hoisted) ----
    const int R0 = tid / BDIM, C0 = tid - R0 * BDIM;
    const int gr0 = rbase + 2 * R0, gc0 = cbase + 2 * C0;
    const bool cok0  = (unsigned)gc0 < 1024u;
    const bool rtop0 = (unsigned)gr0 < 1024u;
    const bool rbot0 = (unsigned)(gr0 + 1) < 1024u;
    const long long o0 = (long long)gr0 * IW + gc0;

    const bool act1 = tid < (BDIM * BDIM - 256);      // 33 threads
    const int t1 = tid + 256;
    const int R1 = t1 / BDIM, C1 = t1 - R1 * BDIM;
    const int gr1 = rbase + 2 * R1, gc1 = cbase + 2 * C1;
    const bool cok1  = act1 && ((unsigned)gc1 < 1024u);
    const bool rtop1 = (unsigned)gr1 < 1024u;
    const bool rbot1 = (unsigned)(gr1 + 1) < 1024u;
    const long long o1 = (long long)gr1 * IW + gc1;

    const float* imgb = img + (size_t)(IMGS_PER_BLOCK * bz) * (IH * IW);
    float* outb = out + (size_t)(IMGS_PER_BLOCK * bz) * (IH * IW);

#pragma unroll 1
    for (int ib = 0; ib < IMGS_PER_BLOCK; ib++) {
        // ---- stage 17x17 block tile (zero-padded) ----
        {
            float2 top = make_float2(0.0f, 0.0f);
            float2 bot = make_float2(0.0f, 0.0f);
            if (cok0) {
                const float* p = imgb + o0;
                if (rtop0) top = *(const float2*)(p);
                if (rbot0) bot = *(const float2*)(p + IW);
            }
            s_blk[tid] = make_float4(top.x, top.y, bot.x, bot.y);
            if (act1) {
                float2 t2 = make_float2(0.0f, 0.0f);
                float2 b2 = make_float2(0.0f, 0.0f);
                if (cok1) {
                    const float* p = imgb + o1;
                    if (rtop1) t2 = *(const float2*)(p);
                    if (rbot1) b2 = *(const float2*)(p + IW);
                }
                s_blk[t1] = make_float4(t2.x, t2.y, b2.x, b2.y);
            }
        }
        __syncthreads();

        // ---- this thread's single patch ----
        const float4 A  = s_blk[sbase];
        const float4 Bq = s_blk[sbase + 1];
        const float4 C  = s_blk[sbase + BDIM];
        const float4 D  = s_blk[sbase + BDIM + 1];

        // conv(2ch) -> relu
        float cv0[4], cv1[4];
#define CONVB(e, B) do { \
        float v0 = fmaf(wc0.x, (B).x, fmaf(wc0.y, (B).y, fmaf(wc0.z, (B).z, fmaf(wc0.w, (B).w, bc.x)))); \
        float v1 = fmaf(wc1.x, (B).x, fmaf(wc1.y, (B).y, fmaf(wc1.z, (B).z, fmaf(wc1.w, (B).w, bc.y)))); \
        cv0[e] = fmaxf(v0, 0.0f); cv1[e] = fmaxf(v1, 0.0f); } while (0)
        CONVB(0, A); CONVB(1, Bq); CONVB(2, C); CONVB(3, D);
#undef CONVB

        // argmax (first-max semantics: strict >)
        int am0 = 0, am1 = 0;
        float mv0 = cv0[0], mv1 = cv1[0];
#pragma unroll
        for (int e = 1; e < 4; e++) {
            if (cv0[e] > mv0) { mv0 = cv0[e]; am0 = e; }
            if (cv1[e] > mv1) { mv1 = cv1[e]; am1 = e; }
        }

        // dense + relu
        const float z0 = fmaxf(fmaf(mv0, wb.x, fmaf(mv1, wb.y, bb.x)), 0.0f);
        const float z1 = fmaxf(fmaf(mv0, wb.z, fmaf(mv1, wb.w, bb.y)), 0.0f);
        const float zz1 = (am0 == am1) ? z1 : 0.0f;

        // 8 live tanh, pre-scaled by hf: value = hf*(tanh+1)
        float th0s[4], th1s[4];
#pragma unroll
        for (int pq = 0; pq < 4; pq++) {
            th0s[pq] = fmaf(tanhf_fast(fmaf(z0, wd0h[pq], fmaf(zz1, wd1h[pq], bdh))), hf, hf);
            th1s[pq] = fmaf(tanhf_fast(fmaf(z1, wd1h[pq], bdh)), hf, hf);
        }

        // build quadrant groups via pure selects
        float4 grp[4];
#pragma unroll
        for (int g = 0; g < 4; g++) {
            const bool p0 = (am0 == g);
            const bool p1 = (am1 == g);
            grp[g].x = p0 ? th0s[0] : (p1 ? th1s[0] : hfc);
            grp[g].y = p0 ? th0s[1] : (p1 ? th1s[1] : hfc);
            grp[g].z = p0 ? th0s[2] : (p1 ? th1s[2] : hfc);
            grp[g].w = p0 ? th0s[3] : (p1 ? th1s[3] : hfc);
        }
        const float4 gTL = grp[0];   // -> above-left cell (combined via shfl+smem)
        const float4 gTR = grp[1];   // -> above cell
        const float4 gBL = grp[2];   // -> left cell (shfl)
        const float4 gBR = grp[3];   // -> own cell (regs)

        // combine TR with right-neighbor's TL, store ONE float4
        float4 sumT;
        sumT.x = gTR.x + __shfl_down_sync(0xffffffffu, gTL.x, 1);
        sumT.y = gTR.y + __shfl_down_sync(0xffffffffu, gTL.y, 1);
        sumT.z = gTR.z + __shfl_down_sync(0xffffffffu, gTL.z, 1);
        sumT.w = gTR.w + __shfl_down_sync(0xffffffffu, gTL.w, 1);
        s_top[tid] = sumT;

        // BL of right-neighbor patch
        float4 nBL;
        nBL.x = __shfl_down_sync(0xffffffffu, gBL.x, 1);
        nBL.y = __shfl_down_sync(0xffffffffu, gBL.y, 1);
        nBL.z = __shfl_down_sync(0xffffffffu, gBL.z, 1);
        nBL.w = __shfl_down_sync(0xffffffffu, gBL.w, 1);

        __syncthreads();

        // ---- gather + store ----
        if (cell_ok) {
            const float4 vT = s_top[tid + 16];   // (TR of patch below) + (TL of below-right)
            const float pix00 = (gBR.x + nBL.x) + vT.x;
            const float pix01 = (gBR.y + nBL.y) + vT.y;
            const float pix10 = (gBR.z + nBL.z) + vT.z;
            const float pix11 = (gBR.w + nBL.w) + vT.w;

            *(float2*)&outb[(size_t)h * IW + w]       = make_float2(pix00 * rcp, pix01 * rcp);
            *(float2*)&outb[(size_t)(h + 1) * IW + w] = make_float2(pix10 * rcp, pix11 * rcp);
        }

        imgb += IH * IW;
        outb += IH * IW;
    }
}

extern "C" void kernel_launch(void* const* d_in, const int* in_sizes, int n_in,
                              void* d_out, int out_size) {
    const float* img    = (const float*)d_in[0];
    const float* w_conv = (const float*)d_in[1];
    const float* b_conv = (const float*)d_in[2];
    const float* W_b    = (const float*)d_in[3];
    const float* b_b    = (const float*)d_in[4];
    const float* W_d    = (const float*)d_in[5];
    const float* b_d    = (const float*)d_in[6];
    float* out = (float*)d_out;

    dim3 grid(35, 35, 2);   // 4 images per block
    dim3 block(256);
    ae_kernel<<<grid, block>>>(img, w_conv, b_conv, W_b, b_b, W_d, b_d, out);
}

// round 8
// speedup vs baseline: 2.8822x; 1.0071x over previous
#include <cuda_runtime.h>

#define IH 1024
#define IW 1024
#define TJ 15              // owned cell rows/cols per block (15x15 cells = 30x30 px)
#define BDIM 17            // halo 2x2-block rows/cols in smem (17x17)
#define IMGS_PER_BLOCK 4

__device__ __forceinline__ float tanhf_fast(float x) {
    float y; asm("tanh.approx.f32 %0, %1;" : "=f"(y) : "f"(x)); return y;
}

__global__ __launch_bounds__(256, 4)
void ae_kernel(const float* __restrict__ img,
               const float* __restrict__ w_conv,  // (2,1,2,2)
               const float* __restrict__ b_conv,  // (2,)
               const float* __restrict__ W_b,     // (2,2)
               const float* __restrict__ b_b,     // (2,)
               const float* __restrict__ W_d,     // (2,1,2,2)
               const float* __restrict__ b_d,     // (1,)
               float* __restrict__ out)
{
    // double-buffered input halo (disjoint 2x2 pixel blocks) and top-group stage
    __shared__ float4 s_blk[2][BDIM * BDIM];   // 2 x 4.6 KB
    __shared__ float4 s_top[2][256];           // 2 x 4 KB

    const int tid = threadIdx.x;
    const int a  = tid >> 4;      // patch/cell row 0..15
    const int cb = tid & 15;      // patch/cell col 0..15
    const int bk = blockIdx.x, bj = blockIdx.y, bz = blockIdx.z;

    const int j0 = bj * TJ;
    const int k0 = bk * TJ;
    const int rbase = 2 * j0 - 2;   // pixel row of block row 0
    const int cbase = 2 * k0 - 2;

    // ---- tiny weights -> registers (uniform, hoisted across all images) ----
    const float4 wc0 = __ldg((const float4*)w_conv);
    const float4 wc1 = __ldg((const float4*)(w_conv + 4));
    const float2 bc  = __ldg((const float2*)b_conv);
    const float4 wb  = __ldg((const float4*)W_b);
    const float2 bb  = __ldg((const float2*)b_b);
    float wd0h[4], wd1h[4];
    {
        const float4 t0 = __ldg((const float4*)W_d);
        const float4 t1 = __ldg((const float4*)(W_d + 4));
        wd0h[0] = t0.x * 0.5f; wd0h[1] = t0.y * 0.5f; wd0h[2] = t0.z * 0.5f; wd0h[3] = t0.w * 0.5f;
        wd1h[0] = t1.x * 0.5f; wd1h[1] = t1.y * 0.5f; wd1h[2] = t1.z * 0.5f; wd1h[3] = t1.w * 0.5f;
    }
    const float bdh = __ldg(b_d) * 0.5f;
    const float thc = tanhf_fast(bdh);      // tanh for inactive quadrants (uniform)

    // ---- per-thread constants (hoisted) ----
    const int jr = j0 + a - 1;              // this thread's patch row
    const int kc = k0 + cb - 1;             // this thread's patch col
    const float hf = ((unsigned)jr <= 510u && (unsigned)kc <= 510u) ? 0.5f : 0.0f;
    const float hfc = fmaf(thc, hf, hf);    // constant quadrant value, pre-scaled

    const int h = 2 * (j0 + a);
    const int w = 2 * (k0 + cb);
    const bool cell_ok = (a < 15) & (cb < 15) & (h < IH) & (w < IW);
    const bool vj1 = (unsigned)jr        <= 510u;
    const bool vj2 = (unsigned)(jr + 1)  <= 510u;
    const bool vk  = (unsigned)kc        <= 510u;
    const bool vkn = (unsigned)(kc + 1)  <= 510u;
    const int cnt = ((int)vj1 + (int)vj2) * ((int)vk + (int)vkn);
    const float rcp = (cnt == 4) ? 0.25f : ((cnt == 2) ? 0.5f : 1.0f);

    const int sbase = a * BDIM + cb;

    // ---- staging addressing (image-invariant, hoisted) ----
    const int R0 = tid / BDIM, C0 = tid - R0 * BDIM;
    const int gr0 = rbase + 2 * R0, gc0 = cbase + 2 * C0;
    const bool cok0  = (unsigned)gc0 < 1024u;
    const bool rtop0 = (unsigned)gr0 < 1024u;
    const bool rbot0 = (unsigned)(gr0 + 1) < 1024u;
    const int o0 = gr0 * IW + gc0;

    const bool act1 = tid < (BDIM * BDIM - 256);      // 33 threads
    const int t1 = tid + 256;
    const int R1 = t1 / BDIM, C1 = t1 - R1 * BDIM;
    const int gr1 = rbase + 2 * R1, gc1 = cbase + 2 * C1;
    const bool cok1  = act1 && ((unsigned)gc1 < 1024u);
    const bool rtop1 = (unsigned)gr1 < 1024u;
    const bool rbot1 = (unsigned)(gr1 + 1) < 1024u;
    const int o1 = gr1 * IW + gc1;

    const float* imgb = img + (size_t)(IMGS_PER_BLOCK * bz) * (IH * IW);
    float* outb = out + (size_t)(IMGS_PER_BLOCK * bz) * (IH * IW);

#define STAGE(buf, base_ptr) do {                                          \
        float2 top_ = make_float2(0.0f, 0.0f);                             \
        float2 bot_ = make_float2(0.0f, 0.0f);                             \
        if (cok0) {                                                        \
            const float* p_ = (base_ptr) + o0;                             \
            if (rtop0) top_ = *(const float2*)(p_);                        \
            if (rbot0) bot_ = *(const float2*)(p_ + IW);                   \
        }                                                                  \
        s_blk[buf][tid] = make_float4(top_.x, top_.y, bot_.x, bot_.y);     \
        if (act1) {                                                        \
            float2 t2_ = make_float2(0.0f, 0.0f);                         \
            float2 b2_ = make_float2(0.0f, 0.0f);                         \
            if (cok1) {                                                    \
                const float* p_ = (base_ptr) + o1;                         \
                if (rtop1) t2_ = *(const float2*)(p_);                     \
                if (rbot1) b2_ = *(const float2*)(p_ + IW);                \
            }                                                              \
            s_blk[buf][t1] = make_float4(t2_.x, t2_.y, b2_.x, b2_.y);      \
        }                                                                  \
    } while (0)

    // ---- prologue: stage image 0 ----
    STAGE(0, imgb);
    __syncthreads();

#pragma unroll
    for (int ib = 0; ib < IMGS_PER_BLOCK; ib++) {
        const int p = ib & 1;

        // ---- stage next image into the other buffer (overlaps with compute) ----
        if (ib < IMGS_PER_BLOCK - 1) {
            STAGE(1 - p, imgb + (ib + 1) * (IH * IW));
        }

        // ---- compute this thread's single patch from blk[p] ----
        const float4 A  = s_blk[p][sbase];
        const float4 Bq = s_blk[p][sbase + 1];
        const float4 C  = s_blk[p][sbase + BDIM];
        const float4 D  = s_blk[p][sbase + BDIM + 1];

        // conv(2ch) -> relu
        float cv0[4], cv1[4];
#define CONVB(e, B) do { \
        float v0 = fmaf(wc0.x, (B).x, fmaf(wc0.y, (B).y, fmaf(wc0.z, (B).z, fmaf(wc0.w, (B).w, bc.x)))); \
        float v1 = fmaf(wc1.x, (B).x, fmaf(wc1.y, (B).y, fmaf(wc1.z, (B).z, fmaf(wc1.w, (B).w, bc.y)))); \
        cv0[e] = fmaxf(v0, 0.0f); cv1[e] = fmaxf(v1, 0.0f); } while (0)
        CONVB(0, A); CONVB(1, Bq); CONVB(2, C); CONVB(3, D);
#undef CONVB

        // argmax (first-max semantics: strict >)
        int am0 = 0, am1 = 0;
        float mv0 = cv0[0], mv1 = cv1[0];
#pragma unroll
        for (int e = 1; e < 4; e++) {
            if (cv0[e] > mv0) { mv0 = cv0[e]; am0 = e; }
            if (cv1[e] > mv1) { mv1 = cv1[e]; am1 = e; }
        }

        // dense + relu
        const float z0 = fmaxf(fmaf(mv0, wb.x, fmaf(mv1, wb.y, bb.x)), 0.0f);
        const float z1 = fmaxf(fmaf(mv0, wb.z, fmaf(mv1, wb.w, bb.y)), 0.0f);
        const float zz1 = (am0 == am1) ? z1 : 0.0f;

        // 8 live tanh, pre-scaled by hf: value = hf*(tanh+1)
        float th0s[4], th1s[4];
#pragma unroll
        for (int pq = 0; pq < 4; pq++) {
            th0s[pq] = fmaf(tanhf_fast(fmaf(z0, wd0h[pq], fmaf(zz1, wd1h[pq], bdh))), hf, hf);
            th1s[pq] = fmaf(tanhf_fast(fmaf(z1, wd1h[pq], bdh)), hf, hf);
        }

        // build quadrant groups via pure selects
        float4 grp[4];
#pragma unroll
        for (int g = 0; g < 4; g++) {
            const bool p0 = (am0 == g);
            const bool p1 = (am1 == g);
            grp[g].x = p0 ? th0s[0] : (p1 ? th1s[0] : hfc);
            grp[g].y = p0 ? th0s[1] : (p1 ? th1s[1] : hfc);
            grp[g].z = p0 ? th0s[2] : (p1 ? th1s[2] : hfc);
            grp[g].w = p0 ? th0s[3] : (p1 ? th1s[3] : hfc);
        }
        const float4 gTL = grp[0];   // -> above-left cell (combined via shfl+smem)
        const float4 gTR = grp[1];   // -> above cell
        const float4 gBL = grp[2];   // -> left cell (shfl)
        const float4 gBR = grp[3];   // -> own cell (regs)

        // combine TR with right-neighbor's TL, store ONE float4
        float4 sumT;
        sumT.x = gTR.x + __shfl_down_sync(0xffffffffu, gTL.x, 1);
        sumT.y = gTR.y + __shfl_down_sync(0xffffffffu, gTL.y, 1);
        sumT.z = gTR.z + __shfl_down_sync(0xffffffffu, gTL.z, 1);
        sumT.w = gTR.w + __shfl_down_sync(0xffffffffu, gTL.w, 1);
        s_top[p][tid] = sumT;

        // BL of right-neighbor patch
        float4 nBL;
        nBL.x = __shfl_down_sync(0xffffffffu, gBL.x, 1);
        nBL.y = __shfl_down_sync(0xffffffffu, gBL.y, 1);
        nBL.z = __shfl_down_sync(0xffffffffu, gBL.z, 1);
        nBL.w = __shfl_down_sync(0xffffffffu, gBL.w, 1);

        __syncthreads();   // single barrier: top[p] ready AND blk[1-p] staged

        // ---- gather + store ----
        if (cell_ok) {
            const float4 vT = s_top[p][tid + 16];   // (TR of patch below) + (TL of below-right)
            const float pix00 = (gBR.x + nBL.x) + vT.x;
            const float pix01 = (gBR.y + nBL.y) + vT.y;
            const float pix10 = (gBR.z + nBL.z) + vT.z;
            const float pix11 = (gBR.w + nBL.w) + vT.w;

            float* op = outb + (size_t)ib * (IH * IW);
            *(float2*)&op[(size_t)h * IW + w]       = make_float2(pix00 * rcp, pix01 * rcp);
            *(float2*)&op[(size_t)(h + 1) * IW + w] = make_float2(pix10 * rcp, pix11 * rcp);
        }
    }
#undef STAGE
}

extern "C" void kernel_launch(void* const* d_in, const int* in_sizes, int n_in,
                              void* d_out, int out_size) {
    const float* img    = (const float*)d_in[0];
    const float* w_conv = (const float*)d_in[1];
    const float* b_conv = (const float*)d_in[2];
    const float* W_b    = (const float*)d_in[3];
    const float* b_b    = (const float*)d_in[4];
    const float* W_d    = (const float*)d_in[5];
    const float* b_d    = (const float*)d_in[6];
    float* out = (float*)d_out;

    dim3 grid(35, 35, 2);   // 4 images per block
    dim3 block(256);
    ae_kernel<<<grid, block>>>(img, w_conv, b_conv, W_b, b_b, W_d, b_d, out);
}